// round 15
// baseline (speedup 1.0000x reference)
#include <cuda_runtime.h>
#include <cuda_fp16.h>

#define NN 100000
#define EE 3200000
#define HH 64
#define NGNB 50000
#define SB 1024
#define NB ((NN + SB - 1) / SB)   // 98 scan blocks
#define PGRID 912                 // 152 SMs x 6 blocks — persistent grid

// Static device scratch. Feature buffers hold 64 halves (128 B) per node.
__device__ uint4  g_bufA[NN * 8];
__device__ uint4  g_bufB[NN * 8];
__device__ uint4  g_vfh[NN];               // fp16-packed input: 6 halves + pad
__device__ unsigned long long g_pack[NN];  // (cnt << 40) | wdeg_fixed26
__device__ float  g_dinv[NN];
__device__ int    g_cnt[NN];
__device__ int    g_rowptr[NN + 1];
__device__ int    g_cursor[NN];
__device__ int2   g_ep[EE];          // packed (src, norm-bits)
__device__ int    g_bsum[NB];
__device__ int    g_boff[NB + 1];

// init packed degree counter + convert vf rows to padded fp16
__global__ void k_init(const float* __restrict__ vf, unsigned long long* pack,
                       uint4* __restrict__ vfh) {
    int i = blockIdx.x * blockDim.x + threadIdx.x;
    if (i < NN) {
        pack[i] = (1ULL << 26);  // self-loop weight 1.0 in 26-bit fixed point
        const float* r = vf + i * 6;
        __half2 h0 = __floats2half2_rn(r[0], r[1]);
        __half2 h1 = __floats2half2_rn(r[2], r[3]);
        __half2 h2 = __floats2half2_rn(r[4], r[5]);
        uint4 v;
        v.x = *(unsigned*)&h0;
        v.y = *(unsigned*)&h1;
        v.z = *(unsigned*)&h2;
        v.w = 0u;
        vfh[i] = v;
    }
}

__global__ void k_hist(const int* __restrict__ dst, const float* __restrict__ w,
                       unsigned long long* __restrict__ pack) {
    int e = blockIdx.x * blockDim.x + threadIdx.x;
    if (e < EE) {
        unsigned long long enc =
            (unsigned long long)__float2uint_rn(w[e] * 67108864.0f) + (1ULL << 40);
        atomicAdd(&pack[dst[e]], enc);
    }
}

// --- multi-block scan (A also unpacks cnt + computes dinv) ---
__global__ void k_scanA(const unsigned long long* __restrict__ pack,
                        int* __restrict__ cnt, float* __restrict__ dinv,
                        int* __restrict__ incl, int* __restrict__ bsum) {
    __shared__ int s[SB];
    int t = threadIdx.x;
    int idx = blockIdx.x * SB + t;
    int v = 0;
    if (idx < NN) {
        unsigned long long p = pack[idx];
        v = (int)(p >> 40);
        cnt[idx] = v;
        float wd = (float)(double)(p & ((1ULL << 40) - 1)) * (1.0f / 67108864.0f);
        dinv[idx] = (wd > 0.0f) ? rsqrtf(wd) : 0.0f;
    }
    s[t] = v;
    __syncthreads();
#pragma unroll
    for (int off = 1; off < SB; off <<= 1) {
        int u = (t >= off) ? s[t - off] : 0;
        __syncthreads();
        s[t] += u;
        __syncthreads();
    }
    if (idx < NN) incl[idx] = s[t];
    if (t == SB - 1) bsum[blockIdx.x] = s[t];
}

__global__ void k_scanB(const int* __restrict__ bsum, int* __restrict__ boff) {
    __shared__ int s[128];
    int t = threadIdx.x;
    int v = (t < NB) ? bsum[t] : 0;
    s[t] = v;
    __syncthreads();
#pragma unroll
    for (int off = 1; off < 128; off <<= 1) {
        int u = (t >= off) ? s[t - off] : 0;
        __syncthreads();
        s[t] += u;
        __syncthreads();
    }
    if (t < NB) boff[t] = s[t] - v;
    if (t == NB - 1) boff[NB] = s[t];
}

__global__ void k_scanC(const int* __restrict__ cnt, int* __restrict__ incl_cursor,
                        const int* __restrict__ boff, int* __restrict__ rowptr) {
    int t = threadIdx.x;
    int idx = blockIdx.x * SB + t;
    if (idx < NN) {
        int e = incl_cursor[idx] - cnt[idx] + boff[blockIdx.x];
        rowptr[idx] = e;
        incl_cursor[idx] = e;
    }
    if (idx == 0) rowptr[NN] = boff[NB];
}

__global__ void k_scatter(const int* __restrict__ src, const int* __restrict__ dst,
                          const float* __restrict__ w, const float* __restrict__ dinv,
                          int* __restrict__ cursor, int2* __restrict__ ep) {
    int e = blockIdx.x * blockDim.x + threadIdx.x;
    if (e < EE) {
        int s = src[e], d = dst[e];
        int pos = atomicAdd(&cursor[d], 1);
        float nrm = dinv[s] * w[e] * dinv[d];
        ep[pos] = make_int2(s, __float_as_int(nrm));
    }
}

__device__ __forceinline__ void addh8(float a[8], uint4 v, float c) {
    const __half2* h = (const __half2*)&v;
#pragma unroll
    for (int i = 0; i < 4; i++) {
        float2 f = __half22float2(h[i]);
        a[2 * i]     += f.x * c;
        a[2 * i + 1] += f.y * c;
    }
}

// Single-node gather, ep prefetch. 8 lanes/edge, 4 edges/iter. Result lanes 0..7.
__device__ __forceinline__ void gather1(const uint4* __restrict__ x8,
                                        const int2* __restrict__ ep,
                                        const int* __restrict__ rowptr,
                                        const float* __restrict__ dinv,
                                        int node, int q, int fl,
                                        float ra[8]) {
#pragma unroll
    for (int i = 0; i < 8; i++) ra[i] = 0.f;
    int beg = rowptr[node], end = rowptr[node + 1];
    if (q == 0) {
        float dv = dinv[node];
        addh8(ra, x8[node * 8 + fl], dv * dv);
    }
    int cnt = end - beg;
    int ca = cnt & ~3;
    int2 pa_n;
    if (ca > 0) pa_n = ep[beg + q];
    for (int t = 0; t < ca; t += 4) {
        int2 pa = pa_n;
        int tn = t + 4;
        if (tn < ca) pa_n = ep[beg + tn + q];
        addh8(ra, x8[(size_t)pa.x * 8 + fl], __int_as_float(pa.y));
    }
    if (q < (cnt & 3)) {
        int2 pa = ep[beg + ca + q];
        addh8(ra, x8[(size_t)pa.x * 8 + fl], __int_as_float(pa.y));
    }
#pragma unroll
    for (int i = 0; i < 8; i++) {
        ra[i] += __shfl_down_sync(0xffffffffu, ra[i], 16);
        ra[i] += __shfl_down_sync(0xffffffffu, ra[i], 8);
    }
}

// Fused, warp-autonomous, PERSISTENT, high-occupancy (256 thr, 6 blocks/SM):
// single node per warp iteration; warps stride over nodes globally.
template <bool LAST>
__global__ void __launch_bounds__(256, 6)
k_pull_xform(const uint4* __restrict__ x8, const int2* __restrict__ ep,
             const int* __restrict__ rowptr, const float* __restrict__ dinv,
             const float* __restrict__ W, const float* __restrict__ bias,
             const float* __restrict__ Wl, const float* __restrict__ bl,
             __half* __restrict__ y, float* __restrict__ out) {
    __shared__ float sW[64 * 64];
    __shared__ float sWl[64 * 5];

    const int nlim = LAST ? NGNB : NN;

    int tid = threadIdx.x;
    int w = tid >> 5, lane = tid & 31;
    int q = lane >> 3, fl = lane & 7;

#pragma unroll
    for (int i = tid; i < 64 * 64; i += 256) sW[i] = W[i];
    if (LAST) {
        for (int i = tid; i < 64 * 5; i += 256) sWl[i] = Wl[i];
    }
    float bias0 = bias[lane], bias1 = bias[lane + 32];
    __syncthreads();  // the only block sync

    int gw = blockIdx.x * 8 + w;
    int nwt = gridDim.x * 8;

#pragma unroll 1
    for (int n = gw; n < nlim; n += nwt) {
        float ra[8];
        gather1(x8, ep, rowptr, dinv, n, q, fl, ra);

        // GEMM: broadcast x from lanes 0..7
        float a0 = bias0, a1 = bias1;
#pragma unroll
        for (int kk = 0; kk < 8; kk++) {
#pragma unroll
            for (int i = 0; i < 8; i++) {
                float sa = __shfl_sync(0xffffffffu, ra[i], kk);
                int k = kk * 8 + i;
                a0 += sa * sW[k * 64 + lane];
                a1 += sa * sW[k * 64 + lane + 32];
            }
        }
        float ya0 = 1.0f / (1.0f + __expf(-a0));
        float ya1 = 1.0f / (1.0f + __expf(-a1));

        if (!LAST) {
            y[n * 64 + lane] = __float2half_rn(ya0);
            y[n * 64 + lane + 32] = __float2half_rn(ya1);
        } else {
            float pr[5];
#pragma unroll
            for (int o = 0; o < 5; o++)
                pr[o] = ya0 * sWl[lane * 5 + o] + ya1 * sWl[(lane + 32) * 5 + o];
#pragma unroll
            for (int o = 0; o < 5; o++)
#pragma unroll
                for (int off = 16; off; off >>= 1)
                    pr[o] += __shfl_down_sync(0xffffffffu, pr[o], off);
            if (lane == 0) {
#pragma unroll
                for (int o = 0; o < 5; o++) out[n * 5 + o] = pr[o] + bl[o];
            }
        }
    }
}

// Layer-1 pull, fp16 input: 8 lanes per node (4 nodes/warp), lane-per-edge.
__global__ void k_pull6h(const uint4* __restrict__ vfh, const int2* __restrict__ ep,
                         const int* __restrict__ rowptr, const float* __restrict__ dinv,
                         float* __restrict__ out) {
    int gid = blockIdx.x * blockDim.x + threadIdx.x;
    int node = gid >> 3, sl = gid & 7;
    if (node >= NN) return;
    int beg = rowptr[node], end = rowptr[node + 1];
    float a[6] = {0.f, 0.f, 0.f, 0.f, 0.f, 0.f};
    for (int j = beg + sl; j < end; j += 8) {
        int2 p = ep[j];
        float c = __int_as_float(p.y);
        uint4 v = vfh[p.x];
        float2 f0 = __half22float2(*(__half2*)&v.x);
        float2 f1 = __half22float2(*(__half2*)&v.y);
        float2 f2 = __half22float2(*(__half2*)&v.z);
        a[0] += f0.x * c; a[1] += f0.y * c;
        a[2] += f1.x * c; a[3] += f1.y * c;
        a[4] += f2.x * c; a[5] += f2.y * c;
    }
    if (sl == 0) {
        float dv = dinv[node];
        float cs = dv * dv;
        uint4 v = vfh[node];
        float2 f0 = __half22float2(*(__half2*)&v.x);
        float2 f1 = __half22float2(*(__half2*)&v.y);
        float2 f2 = __half22float2(*(__half2*)&v.z);
        a[0] += f0.x * cs; a[1] += f0.y * cs;
        a[2] += f1.x * cs; a[3] += f1.y * cs;
        a[4] += f2.x * cs; a[5] += f2.y * cs;
    }
#pragma unroll
    for (int k = 0; k < 6; k++) {
        a[k] += __shfl_down_sync(0xffffffffu, a[k], 4, 8);
        a[k] += __shfl_down_sync(0xffffffffu, a[k], 2, 8);
        a[k] += __shfl_down_sync(0xffffffffu, a[k], 1, 8);
    }
    if (sl == 0) {
#pragma unroll
        for (int k = 0; k < 6; k++) out[node * 6 + k] = a[k];
    }
}

// out[row,:] = half(sigmoid(in[row,:] @ W[6,64] + b)) — 64 rows/block
__global__ void k_xform6(const float* __restrict__ in, const float* __restrict__ W,
                         const float* __restrict__ b, __half* __restrict__ out) {
    __shared__ float sW[6 * 64];
    __shared__ float sx[64][6];
    int tid = threadIdx.x;  // 512
    for (int i = tid; i < 6 * 64; i += 512) sW[i] = W[i];
    int base = blockIdx.x * 64;
    for (int i = tid; i < 64 * 6; i += 512) {
        int r = i / 6, c = i % 6;
        if (base + r < NN) sx[r][c] = in[(base + r) * 6 + c];
    }
    __syncthreads();
    int r0 = tid >> 6, o = tid & 63;
#pragma unroll
    for (int rr = 0; rr < 8; rr++) {
        int r = rr * 8 + r0;
        int row = base + r;
        if (row < NN) {
            float acc = b[o];
#pragma unroll
            for (int k = 0; k < 6; k++) acc += sx[r][k] * sW[k * 64 + o];
            out[row * 64 + o] = __float2half_rn(1.0f / (1.0f + __expf(-acc)));
        }
    }
}

extern "C" void kernel_launch(void* const* d_in, const int* in_sizes, int n_in,
                              void* d_out, int out_size) {
    const float* vf  = (const float*)d_in[0];
    const int*   edg = (const int*)d_in[1];
    const float* w   = (const float*)d_in[2];
    const float* W1  = (const float*)d_in[3];
    const float* b1  = (const float*)d_in[4];
    const float* W2  = (const float*)d_in[5];
    const float* b2  = (const float*)d_in[6];
    const float* W3  = (const float*)d_in[7];
    const float* b3  = (const float*)d_in[8];
    const float* W4  = (const float*)d_in[9];
    const float* b4  = (const float*)d_in[10];
    const float* Wl  = (const float*)d_in[11];
    const float* bl  = (const float*)d_in[12];
    float* out = (float*)d_out;

    const int* src = edg;
    const int* dst = edg + EE;

    uint4 *bufA8, *bufB8, *vfh;
    unsigned long long* pack;
    float *dinv;
    int *cnt, *rowptr, *cursor, *bsum, *boff;
    int2 *ep;
    cudaGetSymbolAddress((void**)&bufA8, g_bufA);
    cudaGetSymbolAddress((void**)&bufB8, g_bufB);
    cudaGetSymbolAddress((void**)&vfh, g_vfh);
    cudaGetSymbolAddress((void**)&pack, g_pack);
    cudaGetSymbolAddress((void**)&dinv, g_dinv);
    cudaGetSymbolAddress((void**)&cnt, g_cnt);
    cudaGetSymbolAddress((void**)&rowptr, g_rowptr);
    cudaGetSymbolAddress((void**)&cursor, g_cursor);
    cudaGetSymbolAddress((void**)&ep, g_ep);
    cudaGetSymbolAddress((void**)&bsum, g_bsum);
    cudaGetSymbolAddress((void**)&boff, g_boff);

    const int T = 256;
    const int gN = (NN + T - 1) / T;
    const int gE = (EE + T - 1) / T;

    // --- CSR build + normalization ---
    k_init<<<gN, T>>>(vf, pack, vfh);
    k_hist<<<gE, T>>>(dst, w, pack);
    k_scanA<<<NB, SB>>>(pack, cnt, dinv, cursor, bsum);
    k_scanB<<<1, 128>>>(bsum, boff);
    k_scanC<<<NB, SB>>>(cnt, cursor, boff, rowptr);
    k_scatter<<<gE, T>>>(src, dst, w, dinv, cursor, ep);

    const int gP6 = (NN * 8 + 511) / 512;
    const int gX  = (NN + 63) / 64;

    // Layer 1: fp16 gather (lane-per-edge) -> fp32 temp -> xform6 -> half in bufB
    k_pull6h<<<gP6, 512>>>(vfh, ep, rowptr, dinv, (float*)bufA8);
    k_xform6<<<gX, 512>>>((float*)bufA8, W1, b1, (__half*)bufB8);

    // Layers 2-4 fused, persistent, high-occupancy (256 thr x 6 blocks/SM)
    k_pull_xform<false><<<PGRID, 256>>>(bufB8, ep, rowptr, dinv, W2, b2,
                                        nullptr, nullptr, (__half*)bufA8, nullptr);
    k_pull_xform<false><<<PGRID, 256>>>(bufA8, ep, rowptr, dinv, W3, b3,
                                        nullptr, nullptr, (__half*)bufB8, nullptr);
    k_pull_xform<true><<<PGRID, 256>>>(bufB8, ep, rowptr, dinv, W4, b4,
                                       Wl, bl, nullptr, out);
}

// round 16
// speedup vs baseline: 1.1364x; 1.1364x over previous
#include <cuda_runtime.h>
#include <cuda_fp16.h>

#define NN 100000
#define EE 3200000
#define HH 64
#define NGNB 50000
#define SB 1024
#define NB ((NN + SB - 1) / SB)   // 98 scan blocks
#define PGRID 608                 // 152 SMs x 4 blocks — persistent grid

typedef unsigned long long ull;

// Static device scratch. Feature buffers hold 64 halves (128 B) per node.
__device__ uint4  g_bufA[NN * 8];
__device__ uint4  g_bufB[NN * 8];
__device__ uint4  g_vfh[NN];               // fp16-packed input: 6 halves + pad
__device__ ull    g_pack[NN];              // (cnt << 40) | wdeg_fixed26
__device__ float  g_dinv[NN];
__device__ int    g_cnt[NN];
__device__ int    g_rowptr[NN + 1];
__device__ int    g_cursor[NN];
__device__ int2   g_ep[EE];          // packed (src, (dinv[src]*w)-bits)
__device__ int    g_bsum[NB];
__device__ int    g_boff[NB + 1];

#define FMA_F32X2(d, a, b, c) \
    asm("fma.rn.f32x2 %0, %1, %2, %3;" : "=l"(d) : "l"(a), "l"(b), "l"(c))

// init packed degree counter + convert vf rows to padded fp16
__global__ void k_init(const float* __restrict__ vf, ull* pack,
                       uint4* __restrict__ vfh) {
    int i = blockIdx.x * blockDim.x + threadIdx.x;
    if (i < NN) {
        pack[i] = (1ULL << 26);  // self-loop weight 1.0 in 26-bit fixed point
        const float* r = vf + i * 6;
        __half2 h0 = __floats2half2_rn(r[0], r[1]);
        __half2 h1 = __floats2half2_rn(r[2], r[3]);
        __half2 h2 = __floats2half2_rn(r[4], r[5]);
        uint4 v;
        v.x = *(unsigned*)&h0;
        v.y = *(unsigned*)&h1;
        v.z = *(unsigned*)&h2;
        v.w = 0u;
        vfh[i] = v;
    }
}

__global__ void k_hist(const int* __restrict__ dst, const float* __restrict__ w,
                       ull* __restrict__ pack) {
    int e = blockIdx.x * blockDim.x + threadIdx.x;
    if (e < EE) {
        ull enc = (ull)__float2uint_rn(w[e] * 67108864.0f) + (1ULL << 40);
        atomicAdd(&pack[dst[e]], enc);
    }
}

// --- multi-block scan (A also unpacks cnt + computes dinv) ---
__global__ void k_scanA(const ull* __restrict__ pack,
                        int* __restrict__ cnt, float* __restrict__ dinv,
                        int* __restrict__ incl, int* __restrict__ bsum) {
    __shared__ int s[SB];
    int t = threadIdx.x;
    int idx = blockIdx.x * SB + t;
    int v = 0;
    if (idx < NN) {
        ull p = pack[idx];
        v = (int)(p >> 40);
        cnt[idx] = v;
        float wd = (float)(double)(p & ((1ULL << 40) - 1)) * (1.0f / 67108864.0f);
        dinv[idx] = (wd > 0.0f) ? rsqrtf(wd) : 0.0f;
    }
    s[t] = v;
    __syncthreads();
#pragma unroll
    for (int off = 1; off < SB; off <<= 1) {
        int u = (t >= off) ? s[t - off] : 0;
        __syncthreads();
        s[t] += u;
        __syncthreads();
    }
    if (idx < NN) incl[idx] = s[t];
    if (t == SB - 1) bsum[blockIdx.x] = s[t];
}

__global__ void k_scanB(const int* __restrict__ bsum, int* __restrict__ boff) {
    __shared__ int s[128];
    int t = threadIdx.x;
    int v = (t < NB) ? bsum[t] : 0;
    s[t] = v;
    __syncthreads();
#pragma unroll
    for (int off = 1; off < 128; off <<= 1) {
        int u = (t >= off) ? s[t - off] : 0;
        __syncthreads();
        s[t] += u;
        __syncthreads();
    }
    if (t < NB) boff[t] = s[t] - v;
    if (t == NB - 1) boff[NB] = s[t];
}

__global__ void k_scanC(const int* __restrict__ cnt, int* __restrict__ incl_cursor,
                        const int* __restrict__ boff, int* __restrict__ rowptr) {
    int t = threadIdx.x;
    int idx = blockIdx.x * SB + t;
    if (idx < NN) {
        int e = incl_cursor[idx] - cnt[idx] + boff[blockIdx.x];
        rowptr[idx] = e;
        incl_cursor[idx] = e;
    }
    if (idx == 0) rowptr[NN] = boff[NB];
}

// scatter edges into CSR (by dst). ep.y = dinv[src]*w — dst factor applied in pulls.
__global__ void k_scatter(const int* __restrict__ src, const int* __restrict__ dst,
                          const float* __restrict__ w, const float* __restrict__ dinv,
                          int* __restrict__ cursor, int2* __restrict__ ep) {
    int e = blockIdx.x * blockDim.x + threadIdx.x;
    if (e < EE) {
        int s = src[e], d = dst[e];
        int pos = atomicAdd(&cursor[d], 1);
        float nrm = dinv[s] * w[e];
        ep[pos] = make_int2(s, __float_as_int(nrm));
    }
}

__device__ __forceinline__ void addh8(float a[8], uint4 v, float c) {
    const __half2* h = (const __half2*)&v;
#pragma unroll
    for (int i = 0; i < 4; i++) {
        float2 f = __half22float2(h[i]);
        a[2 * i]     += f.x * c;
        a[2 * i + 1] += f.y * c;
    }
}

// Interleaved gather for a node pair (R12-proven), ep prefetch.
// ep.y = dinv[src]*w; final result scaled by dinv[node]. Results on lanes 0..7.
__device__ __forceinline__ void gather2(const uint4* __restrict__ x8,
                                        const int2* __restrict__ ep,
                                        const int* __restrict__ rowptr,
                                        const float* __restrict__ dinv,
                                        int na, int nb, int nlim,
                                        int q, int fl,
                                        float ra[8], float rb[8]) {
#pragma unroll
    for (int i = 0; i < 8; i++) { ra[i] = 0.f; rb[i] = 0.f; }
    int bega = 0, enda = 0, begb = 0, endb = 0;
    float dva = 0.f, dvb = 0.f;
    if (na < nlim) {
        bega = rowptr[na]; enda = rowptr[na + 1];
        dva = dinv[na];
        if (q == 0) addh8(ra, x8[na * 8 + fl], dva);   // self: dv*x (outer dv applied later)
    }
    if (nb < nlim) {
        begb = rowptr[nb]; endb = rowptr[nb + 1];
        dvb = dinv[nb];
        if (q == 0) addh8(rb, x8[nb * 8 + fl], dvb);
    }
    int ca = (enda - bega) & ~3, cb = (endb - begb) & ~3;
    int nmin = min(ca, cb);
    int2 pa_n, pb_n;
    if (nmin > 0) {
        pa_n = ep[bega + q];
        pb_n = ep[begb + q];
    }
    for (int t = 0; t < nmin; t += 4) {
        int2 pa = pa_n, pb = pb_n;
        int tn = t + 4;
        if (tn < nmin) {
            pa_n = ep[bega + tn + q];
            pb_n = ep[begb + tn + q];
        }
        addh8(ra, x8[(size_t)pa.x * 8 + fl], __int_as_float(pa.y));
        addh8(rb, x8[(size_t)pb.x * 8 + fl], __int_as_float(pb.y));
    }
    for (int u = nmin; u < ca; u += 4) {
        int2 pa = ep[bega + u + q];
        addh8(ra, x8[(size_t)pa.x * 8 + fl], __int_as_float(pa.y));
    }
    for (int u = nmin; u < cb; u += 4) {
        int2 pb = ep[begb + u + q];
        addh8(rb, x8[(size_t)pb.x * 8 + fl], __int_as_float(pb.y));
    }
    if (q < ((enda - bega) & 3)) {
        int2 pa = ep[bega + ca + q];
        addh8(ra, x8[(size_t)pa.x * 8 + fl], __int_as_float(pa.y));
    }
    if (q < ((endb - begb) & 3)) {
        int2 pb = ep[begb + cb + q];
        addh8(rb, x8[(size_t)pb.x * 8 + fl], __int_as_float(pb.y));
    }
#pragma unroll
    for (int i = 0; i < 8; i++) {
        ra[i] += __shfl_down_sync(0xffffffffu, ra[i], 16);
        ra[i] += __shfl_down_sync(0xffffffffu, ra[i], 8);
        rb[i] += __shfl_down_sync(0xffffffffu, rb[i], 16);
        rb[i] += __shfl_down_sync(0xffffffffu, rb[i], 8);
        ra[i] *= dva;    // apply dinv[dst]
        rb[i] *= dvb;
    }
}

// Fused, warp-autonomous, PERSISTENT (R12 shape). GEMM via smem-broadcast x
// (duplicated float2) + packed-f32x2 W + FFMA2 — no shuffles in the GEMM.
template <bool LAST>
__global__ void __launch_bounds__(512, 2)
k_pull_xform(const uint4* __restrict__ x8, const int2* __restrict__ ep,
             const int* __restrict__ rowptr, const float* __restrict__ dinv,
             const float* __restrict__ W, const float* __restrict__ bias,
             const float* __restrict__ Wl, const float* __restrict__ bl,
             __half* __restrict__ y, float* __restrict__ out) {
    __shared__ float2 sW2[64 * 32];        // (W[k][lane], W[k][lane+32])
    __shared__ float2 sX2[16][2][64];      // per-warp duplicated x rows (a,b)
    __shared__ float  sWl[64 * 5];

    const int nlim = LAST ? NGNB : NN;
    const int npairs = (nlim + 1) >> 1;

    int tid = threadIdx.x;
    int w = tid >> 5, lane = tid & 31;
    int q = lane >> 3, fl = lane & 7;

#pragma unroll
    for (int i = tid; i < 64 * 32; i += 512) {
        int k = i >> 5, o = i & 31;
        sW2[i] = make_float2(W[k * 64 + o], W[k * 64 + o + 32]);
    }
    if (LAST) {
        for (int i = tid; i < 64 * 5; i += 512) sWl[i] = Wl[i];
    }
    float bias0 = bias[lane], bias1 = bias[lane + 32];
    ull bias2;
    asm("mov.b64 %0, {%1,%2};" : "=l"(bias2)
        : "r"(__float_as_uint(bias0)), "r"(__float_as_uint(bias1)));
    __syncthreads();  // the only block sync

    int gw = blockIdx.x * 16 + w;
    int nwt = gridDim.x * 16;

#pragma unroll 1
    for (int p = gw; p < npairs; p += nwt) {
        int na = 2 * p;
        int nb = na + 1;

        float ra[8], rb[8];
        gather2(x8, ep, rowptr, dinv, na, nb, nlim, q, fl, ra, rb);

        // stage x rows to warp-private smem, duplicated for f32x2
        if (q == 0) {
#pragma unroll
            for (int i = 0; i < 8; i++) {
                sX2[w][0][8 * fl + i] = make_float2(ra[i], ra[i]);
                sX2[w][1][8 * fl + i] = make_float2(rb[i], rb[i]);
            }
        }
        __syncwarp();

        // GEMM: per k-step 3 LDS.64 + 2 FFMA2 for the pair
        ull acca = bias2, accb = bias2;
        const ull* xa = (const ull*)&sX2[w][0][0];
        const ull* xb = (const ull*)&sX2[w][1][0];
        const ull* w2 = (const ull*)&sW2[0];
#pragma unroll 16
        for (int k = 0; k < 64; k++) {
            ull va = xa[k];
            ull vb = xb[k];
            ull wk = w2[k * 32 + lane];
            FMA_F32X2(acca, va, wk, acca);
            FMA_F32X2(accb, vb, wk, accb);
        }
        __syncwarp();

        unsigned lo, hi;
        asm("mov.b64 {%0,%1}, %2;" : "=r"(lo), "=r"(hi) : "l"(acca));
        float a0 = __uint_as_float(lo), a1 = __uint_as_float(hi);
        asm("mov.b64 {%0,%1}, %2;" : "=r"(lo), "=r"(hi) : "l"(accb));
        float b0 = __uint_as_float(lo), b1 = __uint_as_float(hi);

        float ya0 = 1.0f / (1.0f + __expf(-a0));
        float ya1 = 1.0f / (1.0f + __expf(-a1));
        float yb0 = 1.0f / (1.0f + __expf(-b0));
        float yb1 = 1.0f / (1.0f + __expf(-b1));

        if (!LAST) {
            if (na < NN) {
                y[na * 64 + lane] = __float2half_rn(ya0);
                y[na * 64 + lane + 32] = __float2half_rn(ya1);
            }
            if (nb < NN) {
                y[nb * 64 + lane] = __float2half_rn(yb0);
                y[nb * 64 + lane + 32] = __float2half_rn(yb1);
            }
        } else {
            if (na < NGNB) {
                float pr[5];
#pragma unroll
                for (int o = 0; o < 5; o++)
                    pr[o] = ya0 * sWl[lane * 5 + o] + ya1 * sWl[(lane + 32) * 5 + o];
#pragma unroll
                for (int o = 0; o < 5; o++)
#pragma unroll
                    for (int off = 16; off; off >>= 1)
                        pr[o] += __shfl_down_sync(0xffffffffu, pr[o], off);
                if (lane == 0) {
#pragma unroll
                    for (int o = 0; o < 5; o++) out[na * 5 + o] = pr[o] + bl[o];
                }
            }
            if (nb < NGNB) {
                float pr[5];
#pragma unroll
                for (int o = 0; o < 5; o++)
                    pr[o] = yb0 * sWl[lane * 5 + o] + yb1 * sWl[(lane + 32) * 5 + o];
#pragma unroll
                for (int o = 0; o < 5; o++)
#pragma unroll
                    for (int off = 16; off; off >>= 1)
                        pr[o] += __shfl_down_sync(0xffffffffu, pr[o], off);
                if (lane == 0) {
#pragma unroll
                    for (int o = 0; o < 5; o++) out[nb * 5 + o] = pr[o] + bl[o];
                }
            }
        }
    }
}

// Layer-1 pull, fp16 input: 8 lanes per node, lane-per-edge.
// ep.y = dinv[src]*w; final scale by dinv[node].
__global__ void k_pull6h(const uint4* __restrict__ vfh, const int2* __restrict__ ep,
                         const int* __restrict__ rowptr, const float* __restrict__ dinv,
                         float* __restrict__ out) {
    int gid = blockIdx.x * blockDim.x + threadIdx.x;
    int node = gid >> 3, sl = gid & 7;
    if (node >= NN) return;
    int beg = rowptr[node], end = rowptr[node + 1];
    float dv = dinv[node];
    float a[6] = {0.f, 0.f, 0.f, 0.f, 0.f, 0.f};
    for (int j = beg + sl; j < end; j += 8) {
        int2 p = ep[j];
        float c = __int_as_float(p.y);
        uint4 v = vfh[p.x];
        float2 f0 = __half22float2(*(__half2*)&v.x);
        float2 f1 = __half22float2(*(__half2*)&v.y);
        float2 f2 = __half22float2(*(__half2*)&v.z);
        a[0] += f0.x * c; a[1] += f0.y * c;
        a[2] += f1.x * c; a[3] += f1.y * c;
        a[4] += f2.x * c; a[5] += f2.y * c;
    }
    if (sl == 0) {
        uint4 v = vfh[node];
        float2 f0 = __half22float2(*(__half2*)&v.x);
        float2 f1 = __half22float2(*(__half2*)&v.y);
        float2 f2 = __half22float2(*(__half2*)&v.z);
        a[0] += f0.x * dv; a[1] += f0.y * dv;
        a[2] += f1.x * dv; a[3] += f1.y * dv;
        a[4] += f2.x * dv; a[5] += f2.y * dv;
    }
#pragma unroll
    for (int k = 0; k < 6; k++) {
        a[k] += __shfl_down_sync(0xffffffffu, a[k], 4, 8);
        a[k] += __shfl_down_sync(0xffffffffu, a[k], 2, 8);
        a[k] += __shfl_down_sync(0xffffffffu, a[k], 1, 8);
    }
    if (sl == 0) {
#pragma unroll
        for (int k = 0; k < 6; k++) out[node * 6 + k] = a[k] * dv;
    }
}

// out[row,:] = half(sigmoid(in[row,:] @ W[6,64] + b)) — 64 rows/block
__global__ void k_xform6(const float* __restrict__ in, const float* __restrict__ W,
                         const float* __restrict__ b, __half* __restrict__ out) {
    __shared__ float sW[6 * 64];
    __shared__ float sx[64][6];
    int tid = threadIdx.x;  // 512
    for (int i = tid; i < 6 * 64; i += 512) sW[i] = W[i];
    int base = blockIdx.x * 64;
    for (int i = tid; i < 64 * 6; i += 512) {
        int r = i / 6, c = i % 6;
        if (base + r < NN) sx[r][c] = in[(base + r) * 6 + c];
    }
    __syncthreads();
    int r0 = tid >> 6, o = tid & 63;
#pragma unroll
    for (int rr = 0; rr < 8; rr++) {
        int r = rr * 8 + r0;
        int row = base + r;
        if (row < NN) {
            float acc = b[o];
#pragma unroll
            for (int k = 0; k < 6; k++) acc += sx[r][k] * sW[k * 64 + o];
            out[row * 64 + o] = __float2half_rn(1.0f / (1.0f + __expf(-acc)));
        }
    }
}

extern "C" void kernel_launch(void* const* d_in, const int* in_sizes, int n_in,
                              void* d_out, int out_size) {
    const float* vf  = (const float*)d_in[0];
    const int*   edg = (const int*)d_in[1];
    const float* w   = (const float*)d_in[2];
    const float* W1  = (const float*)d_in[3];
    const float* b1  = (const float*)d_in[4];
    const float* W2  = (const float*)d_in[5];
    const float* b2  = (const float*)d_in[6];
    const float* W3  = (const float*)d_in[7];
    const float* b3  = (const float*)d_in[8];
    const float* W4  = (const float*)d_in[9];
    const float* b4  = (const float*)d_in[10];
    const float* Wl  = (const float*)d_in[11];
    const float* bl  = (const float*)d_in[12];
    float* out = (float*)d_out;

    const int* src = edg;
    const int* dst = edg + EE;

    uint4 *bufA8, *bufB8, *vfh;
    ull* pack;
    float *dinv;
    int *cnt, *rowptr, *cursor, *bsum, *boff;
    int2 *ep;
    cudaGetSymbolAddress((void**)&bufA8, g_bufA);
    cudaGetSymbolAddress((void**)&bufB8, g_bufB);
    cudaGetSymbolAddress((void**)&vfh, g_vfh);
    cudaGetSymbolAddress((void**)&pack, g_pack);
    cudaGetSymbolAddress((void**)&dinv, g_dinv);
    cudaGetSymbolAddress((void**)&cnt, g_cnt);
    cudaGetSymbolAddress((void**)&rowptr, g_rowptr);
    cudaGetSymbolAddress((void**)&cursor, g_cursor);
    cudaGetSymbolAddress((void**)&ep, g_ep);
    cudaGetSymbolAddress((void**)&bsum, g_bsum);
    cudaGetSymbolAddress((void**)&boff, g_boff);

    const int T = 256;
    const int gN = (NN + T - 1) / T;
    const int gE = (EE + T - 1) / T;

    // --- CSR build + normalization ---
    k_init<<<gN, T>>>(vf, pack, vfh);
    k_hist<<<gE, T>>>(dst, w, pack);
    k_scanA<<<NB, SB>>>(pack, cnt, dinv, cursor, bsum);
    k_scanB<<<1, 128>>>(bsum, boff);
    k_scanC<<<NB, SB>>>(cnt, cursor, boff, rowptr);
    k_scatter<<<gE, T>>>(src, dst, w, dinv, cursor, ep);

    const int gP6 = (NN * 8 + 511) / 512;
    const int gX  = (NN + 63) / 64;

    // Layer 1: fp16 gather (lane-per-edge) -> fp32 temp -> xform6 -> half in bufB
    k_pull6h<<<gP6, 512>>>(vfh, ep, rowptr, dinv, (float*)bufA8);
    k_xform6<<<gX, 512>>>((float*)bufA8, W1, b1, (__half*)bufB8);

    // Layers 2-4 fused, persistent grid (R12 shape), low-instruction GEMM
    k_pull_xform<false><<<PGRID, 512>>>(bufB8, ep, rowptr, dinv, W2, b2,
                                        nullptr, nullptr, (__half*)bufA8, nullptr);
    k_pull_xform<false><<<PGRID, 512>>>(bufA8, ep, rowptr, dinv, W3, b3,
                                        nullptr, nullptr, (__half*)bufB8, nullptr);
    k_pull_xform<true><<<PGRID, 512>>>(bufB8, ep, rowptr, dinv, W4, b4,
                                       Wl, bl, nullptr, out);
}

// round 17
// speedup vs baseline: 1.2052x; 1.0605x over previous
#include <cuda_runtime.h>
#include <cuda_fp16.h>

#define NN 100000
#define EE 3200000
#define HH 64
#define NGNB 50000
#define SB 1024
#define NB ((NN + SB - 1) / SB)   // 98 scan blocks
#define PGRID 608                 // 152 SMs x 4 blocks — persistent grid

typedef unsigned long long ull;

// Static device scratch. Feature buffers hold 64 halves (128 B) per node.
__device__ uint4  g_bufA[NN * 8];
__device__ uint4  g_bufB[NN * 8];
__device__ uint4  g_vfh[NN];               // fp16-packed input: 6 halves + pad
__device__ ull    g_pack[NN];              // (cnt << 40) | wdeg_fixed26
__device__ float  g_dinv[NN];
__device__ int    g_cnt[NN];
__device__ int    g_rowptr[NN + 1];
__device__ int    g_cursor[NN];
__device__ int2   g_ep[EE];          // packed (src, (dinv[src]*w)-bits)
__device__ int    g_bsum[NB];
__device__ int    g_boff[NB + 1];

// init packed degree counter + convert vf rows to padded fp16
__global__ void k_init(const float* __restrict__ vf, ull* pack,
                       uint4* __restrict__ vfh) {
    int i = blockIdx.x * blockDim.x + threadIdx.x;
    if (i < NN) {
        pack[i] = (1ULL << 26);  // self-loop weight 1.0 in 26-bit fixed point
        const float* r = vf + i * 6;
        __half2 h0 = __floats2half2_rn(r[0], r[1]);
        __half2 h1 = __floats2half2_rn(r[2], r[3]);
        __half2 h2 = __floats2half2_rn(r[4], r[5]);
        uint4 v;
        v.x = *(unsigned*)&h0;
        v.y = *(unsigned*)&h1;
        v.z = *(unsigned*)&h2;
        v.w = 0u;
        vfh[i] = v;
    }
}

__global__ void k_hist(const int* __restrict__ dst, const float* __restrict__ w,
                       ull* __restrict__ pack) {
    int e = blockIdx.x * blockDim.x + threadIdx.x;
    if (e < EE) {
        ull enc = (ull)__float2uint_rn(w[e] * 67108864.0f) + (1ULL << 40);
        atomicAdd(&pack[dst[e]], enc);
    }
}

// --- multi-block scan (A also unpacks cnt + computes dinv) ---
__global__ void k_scanA(const ull* __restrict__ pack,
                        int* __restrict__ cnt, float* __restrict__ dinv,
                        int* __restrict__ incl, int* __restrict__ bsum) {
    __shared__ int s[SB];
    int t = threadIdx.x;
    int idx = blockIdx.x * SB + t;
    int v = 0;
    if (idx < NN) {
        ull p = pack[idx];
        v = (int)(p >> 40);
        cnt[idx] = v;
        float wd = (float)(double)(p & ((1ULL << 40) - 1)) * (1.0f / 67108864.0f);
        dinv[idx] = (wd > 0.0f) ? rsqrtf(wd) : 0.0f;
    }
    s[t] = v;
    __syncthreads();
#pragma unroll
    for (int off = 1; off < SB; off <<= 1) {
        int u = (t >= off) ? s[t - off] : 0;
        __syncthreads();
        s[t] += u;
        __syncthreads();
    }
    if (idx < NN) incl[idx] = s[t];
    if (t == SB - 1) bsum[blockIdx.x] = s[t];
}

__global__ void k_scanB(const int* __restrict__ bsum, int* __restrict__ boff) {
    __shared__ int s[128];
    int t = threadIdx.x;
    int v = (t < NB) ? bsum[t] : 0;
    s[t] = v;
    __syncthreads();
#pragma unroll
    for (int off = 1; off < 128; off <<= 1) {
        int u = (t >= off) ? s[t - off] : 0;
        __syncthreads();
        s[t] += u;
        __syncthreads();
    }
    if (t < NB) boff[t] = s[t] - v;
    if (t == NB - 1) boff[NB] = s[t];
}

__global__ void k_scanC(const int* __restrict__ cnt, int* __restrict__ incl_cursor,
                        const int* __restrict__ boff, int* __restrict__ rowptr) {
    int t = threadIdx.x;
    int idx = blockIdx.x * SB + t;
    if (idx < NN) {
        int e = incl_cursor[idx] - cnt[idx] + boff[blockIdx.x];
        rowptr[idx] = e;
        incl_cursor[idx] = e;
    }
    if (idx == 0) rowptr[NN] = boff[NB];
}

// scatter edges into CSR (by dst). ep.y = dinv[src]*w — NO dinv[dst] gather here;
// the dst factor is applied once per node in the pulls.
__global__ void k_scatter(const int* __restrict__ src, const int* __restrict__ dst,
                          const float* __restrict__ w, const float* __restrict__ dinv,
                          int* __restrict__ cursor, int2* __restrict__ ep) {
    int e = blockIdx.x * blockDim.x + threadIdx.x;
    if (e < EE) {
        int s = src[e], d = dst[e];
        int pos = atomicAdd(&cursor[d], 1);
        float nrm = dinv[s] * w[e];
        ep[pos] = make_int2(s, __float_as_int(nrm));
    }
}

__device__ __forceinline__ void addh8(float a[8], uint4 v, float c) {
    const __half2* h = (const __half2*)&v;
#pragma unroll
    for (int i = 0; i < 4; i++) {
        float2 f = __half22float2(h[i]);
        a[2 * i]     += f.x * c;
        a[2 * i + 1] += f.y * c;
    }
}

// Interleaved gather for a node pair (R12-proven), ep prefetch.
// ep.y = dinv[src]*w; self term uses dv; final result scaled by dinv[node].
// 8 lanes/edge, 4 edges/node/iter. Results on lanes 0..7.
__device__ __forceinline__ void gather2(const uint4* __restrict__ x8,
                                        const int2* __restrict__ ep,
                                        const int* __restrict__ rowptr,
                                        const float* __restrict__ dinv,
                                        int na, int nb, int nlim,
                                        int q, int fl,
                                        float ra[8], float rb[8]) {
#pragma unroll
    for (int i = 0; i < 8; i++) { ra[i] = 0.f; rb[i] = 0.f; }
    int bega = 0, enda = 0, begb = 0, endb = 0;
    float dva = 0.f, dvb = 0.f;
    if (na < nlim) {
        bega = rowptr[na]; enda = rowptr[na + 1];
        dva = dinv[na];
        if (q == 0) addh8(ra, x8[na * 8 + fl], dva);  // self: dv*x (outer dv later)
    }
    if (nb < nlim) {
        begb = rowptr[nb]; endb = rowptr[nb + 1];
        dvb = dinv[nb];
        if (q == 0) addh8(rb, x8[nb * 8 + fl], dvb);
    }
    int ca = (enda - bega) & ~3, cb = (endb - begb) & ~3;
    int nmin = min(ca, cb);
    // software-pipelined main loop: prefetch next ep pair before consuming rows
    int2 pa_n, pb_n;
    if (nmin > 0) {
        pa_n = ep[bega + q];
        pb_n = ep[begb + q];
    }
    for (int t = 0; t < nmin; t += 4) {
        int2 pa = pa_n, pb = pb_n;
        int tn = t + 4;
        if (tn < nmin) {
            pa_n = ep[bega + tn + q];
            pb_n = ep[begb + tn + q];
        }
        addh8(ra, x8[(size_t)pa.x * 8 + fl], __int_as_float(pa.y));
        addh8(rb, x8[(size_t)pb.x * 8 + fl], __int_as_float(pb.y));
    }
    for (int u = nmin; u < ca; u += 4) {
        int2 pa = ep[bega + u + q];
        addh8(ra, x8[(size_t)pa.x * 8 + fl], __int_as_float(pa.y));
    }
    for (int u = nmin; u < cb; u += 4) {
        int2 pb = ep[begb + u + q];
        addh8(rb, x8[(size_t)pb.x * 8 + fl], __int_as_float(pb.y));
    }
    if (q < ((enda - bega) & 3)) {
        int2 pa = ep[bega + ca + q];
        addh8(ra, x8[(size_t)pa.x * 8 + fl], __int_as_float(pa.y));
    }
    if (q < ((endb - begb) & 3)) {
        int2 pb = ep[begb + cb + q];
        addh8(rb, x8[(size_t)pb.x * 8 + fl], __int_as_float(pb.y));
    }
#pragma unroll
    for (int i = 0; i < 8; i++) {
        ra[i] += __shfl_down_sync(0xffffffffu, ra[i], 16);
        ra[i] += __shfl_down_sync(0xffffffffu, ra[i], 8);
        rb[i] += __shfl_down_sync(0xffffffffu, rb[i], 16);
        rb[i] += __shfl_down_sync(0xffffffffu, rb[i], 8);
        ra[i] *= dva;    // apply dinv[dst]
        rb[i] *= dvb;
    }
}

// Fused, warp-autonomous, PERSISTENT: warps stride over node pairs globally.
// (Exact R12 champion structure: shuffle-broadcast paired GEMM.)
template <bool LAST>
__global__ void __launch_bounds__(512, 2)
k_pull_xform(const uint4* __restrict__ x8, const int2* __restrict__ ep,
             const int* __restrict__ rowptr, const float* __restrict__ dinv,
             const float* __restrict__ W, const float* __restrict__ bias,
             const float* __restrict__ Wl, const float* __restrict__ bl,
             __half* __restrict__ y, float* __restrict__ out) {
    __shared__ float sW[64 * 64];
    __shared__ float sWl[64 * 5];

    const int nlim = LAST ? NGNB : NN;
    const int npairs = (nlim + 1) >> 1;

    int tid = threadIdx.x;
    int w = tid >> 5, lane = tid & 31;
    int q = lane >> 3, fl = lane & 7;

#pragma unroll
    for (int i = tid; i < 64 * 64; i += 512) sW[i] = W[i];
    if (LAST) {
        for (int i = tid; i < 64 * 5; i += 512) sWl[i] = Wl[i];
    }
    float bias0 = bias[lane], bias1 = bias[lane + 32];
    __syncthreads();  // the only block sync

    int gw = blockIdx.x * 16 + w;
    int nwt = gridDim.x * 16;

#pragma unroll 1
    for (int p = gw; p < npairs; p += nwt) {
        int na = 2 * p;
        int nb = na + 1;

        float ra[8], rb[8];
        gather2(x8, ep, rowptr, dinv, na, nb, nlim, q, fl, ra, rb);

        // paired GEMM: broadcast x from lanes 0..7, share sW loads
        float a0 = bias0, a1 = bias1, b0 = bias0, b1 = bias1;
#pragma unroll
        for (int kk = 0; kk < 8; kk++) {
#pragma unroll
            for (int i = 0; i < 8; i++) {
                float sa = __shfl_sync(0xffffffffu, ra[i], kk);
                float sb = __shfl_sync(0xffffffffu, rb[i], kk);
                int k = kk * 8 + i;
                float w0 = sW[k * 64 + lane], w1 = sW[k * 64 + lane + 32];
                a0 += sa * w0; a1 += sa * w1;
                b0 += sb * w0; b1 += sb * w1;
            }
        }
        float ya0 = 1.0f / (1.0f + __expf(-a0));
        float ya1 = 1.0f / (1.0f + __expf(-a1));
        float yb0 = 1.0f / (1.0f + __expf(-b0));
        float yb1 = 1.0f / (1.0f + __expf(-b1));

        if (!LAST) {
            if (na < NN) {
                y[na * 64 + lane] = __float2half_rn(ya0);
                y[na * 64 + lane + 32] = __float2half_rn(ya1);
            }
            if (nb < NN) {
                y[nb * 64 + lane] = __float2half_rn(yb0);
                y[nb * 64 + lane + 32] = __float2half_rn(yb1);
            }
        } else {
            if (na < NGNB) {
                float pr[5];
#pragma unroll
                for (int o = 0; o < 5; o++)
                    pr[o] = ya0 * sWl[lane * 5 + o] + ya1 * sWl[(lane + 32) * 5 + o];
#pragma unroll
                for (int o = 0; o < 5; o++)
#pragma unroll
                    for (int off = 16; off; off >>= 1)
                        pr[o] += __shfl_down_sync(0xffffffffu, pr[o], off);
                if (lane == 0) {
#pragma unroll
                    for (int o = 0; o < 5; o++) out[na * 5 + o] = pr[o] + bl[o];
                }
            }
            if (nb < NGNB) {
                float pr[5];
#pragma unroll
                for (int o = 0; o < 5; o++)
                    pr[o] = yb0 * sWl[lane * 5 + o] + yb1 * sWl[(lane + 32) * 5 + o];
#pragma unroll
                for (int o = 0; o < 5; o++)
#pragma unroll
                    for (int off = 16; off; off >>= 1)
                        pr[o] += __shfl_down_sync(0xffffffffu, pr[o], off);
                if (lane == 0) {
#pragma unroll
                    for (int o = 0; o < 5; o++) out[nb * 5 + o] = pr[o] + bl[o];
                }
            }
        }
    }
}

// Layer-1 pull, fp16 input: 8 lanes per node, lane-per-edge.
// ep.y = dinv[src]*w; final scale by dinv[node].
__global__ void k_pull6h(const uint4* __restrict__ vfh, const int2* __restrict__ ep,
                         const int* __restrict__ rowptr, const float* __restrict__ dinv,
                         float* __restrict__ out) {
    int gid = blockIdx.x * blockDim.x + threadIdx.x;
    int node = gid >> 3, sl = gid & 7;
    if (node >= NN) return;
    int beg = rowptr[node], end = rowptr[node + 1];
    float dv = dinv[node];
    float a[6] = {0.f, 0.f, 0.f, 0.f, 0.f, 0.f};
    for (int j = beg + sl; j < end; j += 8) {
        int2 p = ep[j];
        float c = __int_as_float(p.y);
        uint4 v = vfh[p.x];
        float2 f0 = __half22float2(*(__half2*)&v.x);
        float2 f1 = __half22float2(*(__half2*)&v.y);
        float2 f2 = __half22float2(*(__half2*)&v.z);
        a[0] += f0.x * c; a[1] += f0.y * c;
        a[2] += f1.x * c; a[3] += f1.y * c;
        a[4] += f2.x * c; a[5] += f2.y * c;
    }
    if (sl == 0) {
        uint4 v = vfh[node];
        float2 f0 = __half22float2(*(__half2*)&v.x);
        float2 f1 = __half22float2(*(__half2*)&v.y);
        float2 f2 = __half22float2(*(__half2*)&v.z);
        a[0] += f0.x * dv; a[1] += f0.y * dv;
        a[2] += f1.x * dv; a[3] += f1.y * dv;
        a[4] += f2.x * dv; a[5] += f2.y * dv;
    }
#pragma unroll
    for (int k = 0; k < 6; k++) {
        a[k] += __shfl_down_sync(0xffffffffu, a[k], 4, 8);
        a[k] += __shfl_down_sync(0xffffffffu, a[k], 2, 8);
        a[k] += __shfl_down_sync(0xffffffffu, a[k], 1, 8);
    }
    if (sl == 0) {
#pragma unroll
        for (int k = 0; k < 6; k++) out[node * 6 + k] = a[k] * dv;
    }
}

// out[row,:] = half(sigmoid(in[row,:] @ W[6,64] + b)) — 64 rows/block
__global__ void k_xform6(const float* __restrict__ in, const float* __restrict__ W,
                         const float* __restrict__ b, __half* __restrict__ out) {
    __shared__ float sW[6 * 64];
    __shared__ float sx[64][6];
    int tid = threadIdx.x;  // 512
    for (int i = tid; i < 6 * 64; i += 512) sW[i] = W[i];
    int base = blockIdx.x * 64;
    for (int i = tid; i < 64 * 6; i += 512) {
        int r = i / 6, c = i % 6;
        if (base + r < NN) sx[r][c] = in[(base + r) * 6 + c];
    }
    __syncthreads();
    int r0 = tid >> 6, o = tid & 63;
#pragma unroll
    for (int rr = 0; rr < 8; rr++) {
        int r = rr * 8 + r0;
        int row = base + r;
        if (row < NN) {
            float acc = b[o];
#pragma unroll
            for (int k = 0; k < 6; k++) acc += sx[r][k] * sW[k * 64 + o];
            out[row * 64 + o] = __float2half_rn(1.0f / (1.0f + __expf(-acc)));
        }
    }
}

extern "C" void kernel_launch(void* const* d_in, const int* in_sizes, int n_in,
                              void* d_out, int out_size) {
    const float* vf  = (const float*)d_in[0];
    const int*   edg = (const int*)d_in[1];
    const float* w   = (const float*)d_in[2];
    const float* W1  = (const float*)d_in[3];
    const float* b1  = (const float*)d_in[4];
    const float* W2  = (const float*)d_in[5];
    const float* b2  = (const float*)d_in[6];
    const float* W3  = (const float*)d_in[7];
    const float* b3  = (const float*)d_in[8];
    const float* W4  = (const float*)d_in[9];
    const float* b4  = (const float*)d_in[10];
    const float* Wl  = (const float*)d_in[11];
    const float* bl  = (const float*)d_in[12];
    float* out = (float*)d_out;

    const int* src = edg;
    const int* dst = edg + EE;

    uint4 *bufA8, *bufB8, *vfh;
    ull* pack;
    float *dinv;
    int *cnt, *rowptr, *cursor, *bsum, *boff;
    int2 *ep;
    cudaGetSymbolAddress((void**)&bufA8, g_bufA);
    cudaGetSymbolAddress((void**)&bufB8, g_bufB);
    cudaGetSymbolAddress((void**)&vfh, g_vfh);
    cudaGetSymbolAddress((void**)&pack, g_pack);
    cudaGetSymbolAddress((void**)&dinv, g_dinv);
    cudaGetSymbolAddress((void**)&cnt, g_cnt);
    cudaGetSymbolAddress((void**)&rowptr, g_rowptr);
    cudaGetSymbolAddress((void**)&cursor, g_cursor);
    cudaGetSymbolAddress((void**)&ep, g_ep);
    cudaGetSymbolAddress((void**)&bsum, g_bsum);
    cudaGetSymbolAddress((void**)&boff, g_boff);

    const int T = 256;
    const int gN = (NN + T - 1) / T;
    const int gE = (EE + T - 1) / T;

    // --- CSR build + normalization ---
    k_init<<<gN, T>>>(vf, pack, vfh);
    k_hist<<<gE, T>>>(dst, w, pack);
    k_scanA<<<NB, SB>>>(pack, cnt, dinv, cursor, bsum);
    k_scanB<<<1, 128>>>(bsum, boff);
    k_scanC<<<NB, SB>>>(cnt, cursor, boff, rowptr);
    k_scatter<<<gE, T>>>(src, dst, w, dinv, cursor, ep);

    const int gP6 = (NN * 8 + 511) / 512;
    const int gX  = (NN + 63) / 64;

    // Layer 1: fp16 gather (lane-per-edge) -> fp32 temp -> xform6 -> half in bufB
    k_pull6h<<<gP6, 512>>>(vfh, ep, rowptr, dinv, (float*)bufA8);
    k_xform6<<<gX, 512>>>((float*)bufA8, W1, b1, (__half*)bufB8);

    // Layers 2-4 fused, persistent grid (exact R12 champion structure)
    k_pull_xform<false><<<PGRID, 512>>>(bufB8, ep, rowptr, dinv, W2, b2,
                                        nullptr, nullptr, (__half*)bufA8, nullptr);
    k_pull_xform<false><<<PGRID, 512>>>(bufA8, ep, rowptr, dinv, W3, b3,
                                        nullptr, nullptr, (__half*)bufB8, nullptr);
    k_pull_xform<true><<<PGRID, 512>>>(bufB8, ep, rowptr, dinv, W4, b4,
                                       Wl, bl, nullptr, out);
}